// round 6
// baseline (speedup 1.0000x reference)
#include <cuda_runtime.h>
#include <cuda_bf16.h>

#define BB 8
#define NN 2048
#define DD 128

// 1/(2*sqrt(128)): reference scales A by 1/sqrt(D) then entmax divides by 2.
// Folded into Q at projection epilogue.
#define ENTMAX_SCALE 0.04419417382415922f

// Static scratch (no alloc allowed): split-bf16 Q/K and fp32 logits.
__device__ __nv_bfloat16 g_Qh[BB * NN * DD];
__device__ __nv_bfloat16 g_Ql[BB * NN * DD];
__device__ __nv_bfloat16 g_Kh[BB * NN * DD];
__device__ __nv_bfloat16 g_Kl[BB * NN * DD];
__device__ float        g_A[(long)BB * NN * NN];   // 134 MB raw logits

__device__ __forceinline__ unsigned smem_u32(const void* p) {
    unsigned a;
    asm("{ .reg .u64 t; cvta.to.shared.u64 t, %1; cvt.u32.u64 %0, t; }"
        : "=r"(a) : "l"(p));
    return a;
}

#define LDSM_X4(r0, r1, r2, r3, addr) \
    asm volatile("ldmatrix.sync.aligned.m8n8.x4.shared.b16 {%0,%1,%2,%3}, [%4];" \
                 : "=r"(r0), "=r"(r1), "=r"(r2), "=r"(r3) : "r"(addr))

#define MMA_BF16(c, a0, a1, a2, a3, b0, b1) \
    asm volatile("mma.sync.aligned.m16n8k16.row.col.f32.bf16.bf16.f32 " \
                 "{%0,%1,%2,%3}, {%4,%5,%6,%7}, {%8,%9}, {%0,%1,%2,%3};" \
                 : "+f"((c)[0]), "+f"((c)[1]), "+f"((c)[2]), "+f"((c)[3]) \
                 : "r"(a0), "r"(a1), "r"(a2), "r"(a3), "r"(b0), "r"(b1))

// Shared tile geometry (both MMA kernels)
#define PITCH_B 272                  // bytes per 128-half row (17x16B: ldsm conflict-free)
#define T_BYTES (128 * PITCH_B)      // 34816 per tile
#define G_SMEM  (4 * T_BYTES + 512)  // 4 tiles + bias

// ---------------------------------------------------------------------------
// Split a float4 into hi/lo bf16x2 pairs (packed as uint2 for 8B smem stores)
// ---------------------------------------------------------------------------
__device__ __forceinline__ void split4(float4 v, uint2& hh, uint2& ll)
{
    __nv_bfloat162 pa = __floats2bfloat162_rn(v.x, v.y);
    __nv_bfloat162 pb = __floats2bfloat162_rn(v.z, v.w);
    __nv_bfloat162 la = __floats2bfloat162_rn(v.x - __low2float(pa),
                                              v.y - __high2float(pa));
    __nv_bfloat162 lb = __floats2bfloat162_rn(v.z - __low2float(pb),
                                              v.w - __high2float(pb));
    hh.x = *reinterpret_cast<unsigned*>(&pa);
    hh.y = *reinterpret_cast<unsigned*>(&pb);
    ll.x = *reinterpret_cast<unsigned*>(&la);
    ll.y = *reinterpret_cast<unsigned*>(&lb);
}

// ---------------------------------------------------------------------------
// Kernel 1: projection via split-bf16 HMMA.
//   out[r][d] = sum_k x[r][k] * W[d][k] + b[d]   (x: A operand, W: B operand)
// CTA tile M=128 rows x N=128 (all d), K=128. blockIdx<128 -> Q, else K.
// Staging converts fp32 -> hi/lo bf16 tiles on the fly.
// ---------------------------------------------------------------------------
#define SM_AH   0
#define SM_AL   (T_BYTES)
#define SM_BH   (2 * T_BYTES)
#define SM_BL   (3 * T_BYTES)
#define SM_BIAS (4 * T_BYTES)

__global__ void __launch_bounds__(256, 1)
proj_mma_kernel(const float* __restrict__ x_c,
                const float* __restrict__ x_n,
                const float* __restrict__ Wq,
                const float* __restrict__ bq,
                const float* __restrict__ Wk,
                const float* __restrict__ bk)
{
    extern __shared__ char smem[];
    const unsigned sb = smem_u32(smem);
    const int tid  = threadIdx.x;
    const int wid  = tid >> 5;
    const int lane = tid & 31;
    const int wm   = (wid & 3) * 32;
    const int wn   = (wid >> 2) * 64;

    const int which = (blockIdx.x >= 128);
    const int row0  = (blockIdx.x & 127) * 128;        // global row in [0,16384)
    const float* x    = which ? x_n : x_c;
    const float* W    = which ? Wk  : Wq;
    const float* bias = which ? bk  : bq;
    __nv_bfloat16* oh = which ? g_Kh : g_Qh;
    __nv_bfloat16* ol = which ? g_Kl : g_Ql;
    const float scale = which ? 1.0f : ENTMAX_SCALE;

    // Stage x tile (M rows) and W tile (N rows), splitting fp32 -> hi/lo bf16.
    {
        const float4* xs = (const float4*)(x + (long)row0 * DD);
        const float4* ws = (const float4*)W;
        #pragma unroll
        for (int i = 0; i < 16; i++) {
            int idx = i * 256 + tid;            // idx = row*32 + c4
            int r = idx >> 5, c4 = idx & 31;
            uint2 hh, ll;
            split4(xs[idx], hh, ll);
            *(uint2*)(smem + SM_AH + r * PITCH_B + c4 * 8) = hh;
            *(uint2*)(smem + SM_AL + r * PITCH_B + c4 * 8) = ll;
            split4(ws[idx], hh, ll);
            *(uint2*)(smem + SM_BH + r * PITCH_B + c4 * 8) = hh;
            *(uint2*)(smem + SM_BL + r * PITCH_B + c4 * 8) = ll;
        }
        if (tid < 128) ((float*)(smem + SM_BIAS))[tid] = bias[tid];
    }
    __syncthreads();

    float acc[2][8][4];
    #pragma unroll
    for (int mt = 0; mt < 2; mt++)
        #pragma unroll
        for (int nt = 0; nt < 8; nt++)
            #pragma unroll
            for (int j = 0; j < 4; j++) acc[mt][nt][j] = 0.f;

    const int lrow = lane & 15;
    const int lcol = (lane >> 4) * 8;

    #pragma unroll
    for (int pass = 0; pass < 3; pass++) {
        const int aoff = (pass == 2) ? SM_AL : SM_AH;
        const int boff = (pass == 1) ? SM_BL : SM_BH;

        unsigned a[2][8][4];
        #pragma unroll
        for (int mt = 0; mt < 2; mt++)
            #pragma unroll
            for (int kt = 0; kt < 8; kt++) {
                unsigned addr = sb + aoff + (wm + mt * 16 + lrow) * PITCH_B
                              + (kt * 16 + lcol) * 2;
                LDSM_X4(a[mt][kt][0], a[mt][kt][1], a[mt][kt][2], a[mt][kt][3], addr);
            }

        #pragma unroll
        for (int ntp = 0; ntp < 4; ntp++) {
            #pragma unroll
            for (int kt = 0; kt < 8; kt++) {
                unsigned b0, b1, b2, b3;
                unsigned addr = sb + boff + (wn + ntp * 16 + lrow) * PITCH_B
                              + (kt * 16 + lcol) * 2;
                LDSM_X4(b0, b1, b2, b3, addr);
                #pragma unroll
                for (int mt = 0; mt < 2; mt++) {
                    MMA_BF16(acc[mt][2 * ntp + 0], a[mt][kt][0], a[mt][kt][1],
                             a[mt][kt][2], a[mt][kt][3], b0, b2);
                    MMA_BF16(acc[mt][2 * ntp + 1], a[mt][kt][0], a[mt][kt][1],
                             a[mt][kt][2], a[mt][kt][3], b1, b3);
                }
            }
        }
    }

    // Epilogue: +bias, *scale, split to hi/lo bf16, store [row][d].
    const int crow = lane >> 2;
    const int ccol = (lane & 3) * 2;
    const float* bs = (const float*)(smem + SM_BIAS);
    #pragma unroll
    for (int mt = 0; mt < 2; mt++)
        #pragma unroll
        for (int nt = 0; nt < 8; nt++) {
            int col = wn + nt * 8 + ccol;
            float b0 = bs[col], b1 = bs[col + 1];
            #pragma unroll
            for (int half = 0; half < 2; half++) {
                long row = row0 + wm + mt * 16 + crow + half * 8;
                float v0 = (acc[mt][nt][2 * half + 0] + b0) * scale;
                float v1 = (acc[mt][nt][2 * half + 1] + b1) * scale;
                __nv_bfloat162 ph = __floats2bfloat162_rn(v0, v1);
                __nv_bfloat162 pl = __floats2bfloat162_rn(v0 - __low2float(ph),
                                                          v1 - __high2float(ph));
                *(__nv_bfloat162*)(oh + row * DD + col) = ph;
                *(__nv_bfloat162*)(ol + row * DD + col) = pl;
            }
        }
}

// ---------------------------------------------------------------------------
// Kernel 2: split-bf16 HMMA GEMM  g_A[b][m][n] = Qs[b,m] . K[b,n]
// CTA: 256 threads (8 warps, 4x2), tile M=128 x N=128, K=128 resident.
// ---------------------------------------------------------------------------
#define SM_QH   0
#define SM_QL   (T_BYTES)
#define SM_KH   (2 * T_BYTES)
#define SM_KL   (3 * T_BYTES)

__device__ __forceinline__ void stage_tile(char* smem, int off,
                                           const __nv_bfloat16* src, int tid)
{
    const uint4* s = (const uint4*)src;          // 8 halves per uint4
    #pragma unroll
    for (int i = 0; i < 8; i++) {
        int idx = i * 256 + tid;                 // idx = row*16 + c8
        int row = idx >> 4, c8 = idx & 15;
        *(uint4*)(smem + off + row * PITCH_B + c8 * 16) = s[idx];
    }
}

__global__ void __launch_bounds__(256, 1)
qk_mma_kernel()
{
    extern __shared__ char smem[];
    const unsigned sb = smem_u32(smem);
    const int tid  = threadIdx.x;
    const int wid  = tid >> 5;
    const int lane = tid & 31;
    const int wm   = (wid & 3) * 32;
    const int wn   = (wid >> 2) * 64;

    const int b   = blockIdx.x >> 8;
    const int rem = blockIdx.x & 255;
    const int m0  = (rem >> 4) << 7;
    const int n0  = (rem & 15) << 7;

    const long qb = (long)(b * NN + m0) * DD;
    const long kb = (long)(b * NN + n0) * DD;
    stage_tile(smem, SM_QH, g_Qh + qb, tid);
    stage_tile(smem, SM_QL, g_Ql + qb, tid);
    stage_tile(smem, SM_KH, g_Kh + kb, tid);
    stage_tile(smem, SM_KL, g_Kl + kb, tid);
    __syncthreads();

    float acc[2][8][4];
    #pragma unroll
    for (int mt = 0; mt < 2; mt++)
        #pragma unroll
        for (int nt = 0; nt < 8; nt++)
            #pragma unroll
            for (int j = 0; j < 4; j++) acc[mt][nt][j] = 0.f;

    const int lrow = lane & 15;
    const int lcol = (lane >> 4) * 8;

    #pragma unroll
    for (int pass = 0; pass < 3; pass++) {
        const int qoff = (pass == 2) ? SM_QL : SM_QH;
        const int koff = (pass == 1) ? SM_KL : SM_KH;

        unsigned a[2][8][4];
        #pragma unroll
        for (int mt = 0; mt < 2; mt++)
            #pragma unroll
            for (int kt = 0; kt < 8; kt++) {
                unsigned addr = sb + qoff + (wm + mt * 16 + lrow) * PITCH_B
                              + (kt * 16 + lcol) * 2;
                LDSM_X4(a[mt][kt][0], a[mt][kt][1], a[mt][kt][2], a[mt][kt][3], addr);
            }

        #pragma unroll
        for (int ntp = 0; ntp < 4; ntp++) {
            #pragma unroll
            for (int kt = 0; kt < 8; kt++) {
                unsigned b0, b1, b2, b3;
                unsigned addr = sb + koff + (wn + ntp * 16 + lrow) * PITCH_B
                              + (kt * 16 + lcol) * 2;
                LDSM_X4(b0, b1, b2, b3, addr);
                #pragma unroll
                for (int mt = 0; mt < 2; mt++) {
                    MMA_BF16(acc[mt][2 * ntp + 0], a[mt][kt][0], a[mt][kt][1],
                             a[mt][kt][2], a[mt][kt][3], b0, b2);
                    MMA_BF16(acc[mt][2 * ntp + 1], a[mt][kt][0], a[mt][kt][1],
                             a[mt][kt][2], a[mt][kt][3], b1, b3);
                }
            }
        }
    }

    const int crow = lane >> 2;
    const int ccol = (lane & 3) * 2;
    float* base = g_A + (long)(b * NN + m0 + wm) * NN + n0 + wn;
    #pragma unroll
    for (int mt = 0; mt < 2; mt++)
        #pragma unroll
        for (int nt = 0; nt < 8; nt++) {
            float* p0 = base + (long)(mt * 16 + crow) * NN + nt * 8 + ccol;
            *(float2*)p0              = make_float2(acc[mt][nt][0], acc[mt][nt][1]);
            *(float2*)(p0 + 8LL * NN) = make_float2(acc[mt][nt][2], acc[mt][nt][3]);
        }
}

// ---------------------------------------------------------------------------
// Kernel 3: 1.5-entmax per row (sort-free monotone Newton), streaming g_A.
// ---------------------------------------------------------------------------
__global__ void __launch_bounds__(256)
entmax_kernel(float* __restrict__ out)
{
    const int tid = threadIdx.x;
    const int tx  = tid & 31;
    const int wy  = tid >> 5;
    const long row = (long)(blockIdx.x >> 8) * NN + (blockIdx.x & 255) * 8 + wy;

    const float4* src = (const float4*)(g_A + row * NN);
    float acc[64];
    float zmax = -1e30f;
    #pragma unroll
    for (int t = 0; t < 16; t++) {
        float4 v = src[t * 32 + tx];
        acc[t*4+0] = v.x; acc[t*4+1] = v.y; acc[t*4+2] = v.z; acc[t*4+3] = v.w;
        zmax = fmaxf(zmax, fmaxf(fmaxf(v.x, v.y), fmaxf(v.z, v.w)));
    }
    #pragma unroll
    for (int o = 16; o; o >>= 1)
        zmax = fmaxf(zmax, __shfl_xor_sync(0xffffffffu, zmax, o));
    #pragma unroll
    for (int i = 0; i < 64; i++) acc[i] -= zmax;

    // tau = root of f(tau) = sum((z-tau)_+^2) - 1 (convex, decreasing);
    // monotone Newton from tau=-1 never overshoots.
    float tau = -1.0f;
    for (int it = 0; it < 50; it++) {
        float s1 = 0.f, s2 = 0.f;
        #pragma unroll
        for (int i = 0; i < 64; i++) {
            float d = fmaxf(acc[i] - tau, 0.f);
            s1 += d;
            s2 = fmaf(d, d, s2);
        }
        #pragma unroll
        for (int o = 16; o; o >>= 1) {
            s1 += __shfl_xor_sync(0xffffffffu, s1, o);
            s2 += __shfl_xor_sync(0xffffffffu, s2, o);
        }
        float f = s2 - 1.0f;
        if (f < 1e-5f) break;
        tau += f / (2.0f * s1);
    }

    float4* dst = (float4*)(out + row * NN);
    #pragma unroll
    for (int t = 0; t < 16; t++) {
        float d0 = fmaxf(acc[t*4+0] - tau, 0.f);
        float d1 = fmaxf(acc[t*4+1] - tau, 0.f);
        float d2 = fmaxf(acc[t*4+2] - tau, 0.f);
        float d3 = fmaxf(acc[t*4+3] - tau, 0.f);
        dst[t * 32 + tx] = make_float4(d0*d0, d1*d1, d2*d2, d3*d3);
    }
}

// ---------------------------------------------------------------------------
extern "C" void kernel_launch(void* const* d_in, const int* in_sizes, int n_in,
                              void* d_out, int out_size)
{
    const float* x_c = (const float*)d_in[0];
    const float* x_n = (const float*)d_in[1];
    const float* Wq  = (const float*)d_in[2];
    const float* bq  = (const float*)d_in[3];
    const float* Wk  = (const float*)d_in[4];
    const float* bk  = (const float*)d_in[5];

    cudaFuncSetAttribute(proj_mma_kernel,
                         cudaFuncAttributeMaxDynamicSharedMemorySize, G_SMEM);
    cudaFuncSetAttribute(qk_mma_kernel,
                         cudaFuncAttributeMaxDynamicSharedMemorySize, G_SMEM);

    proj_mma_kernel<<<256, 256, G_SMEM>>>(x_c, x_n, Wq, bq, Wk, bk);
    qk_mma_kernel<<<BB * 256, 256, G_SMEM>>>();
    entmax_kernel<<<BB * (NN / 8), 256>>>((float*)d_out);
}

// round 8
// speedup vs baseline: 1.4105x; 1.4105x over previous
#include <cuda_runtime.h>
#include <cuda_bf16.h>

#define BB 8
#define NN 2048
#define DD 128

// 1/(2*sqrt(128)): reference scales A by 1/sqrt(D) then entmax divides by 2.
// Folded into Q at projection epilogue.
#define ENTMAX_SCALE 0.04419417382415922f

// Static scratch (no alloc allowed): split-bf16 Q/K and fp32 logits.
__device__ __nv_bfloat16 g_Qh[BB * NN * DD];
__device__ __nv_bfloat16 g_Ql[BB * NN * DD];
__device__ __nv_bfloat16 g_Kh[BB * NN * DD];
__device__ __nv_bfloat16 g_Kl[BB * NN * DD];
__device__ float        g_A[(long)BB * NN * NN];   // 134 MB raw logits

__device__ __forceinline__ unsigned smem_u32(const void* p) {
    unsigned a;
    asm("{ .reg .u64 t; cvta.to.shared.u64 t, %1; cvt.u32.u64 %0, t; }"
        : "=r"(a) : "l"(p));
    return a;
}

#define LDSM_X4(r0, r1, r2, r3, addr) \
    asm volatile("ldmatrix.sync.aligned.m8n8.x4.shared.b16 {%0,%1,%2,%3}, [%4];" \
                 : "=r"(r0), "=r"(r1), "=r"(r2), "=r"(r3) : "r"(addr))

#define MMA_BF16(c, a0, a1, a2, a3, b0, b1) \
    asm volatile("mma.sync.aligned.m16n8k16.row.col.f32.bf16.bf16.f32 " \
                 "{%0,%1,%2,%3}, {%4,%5,%6,%7}, {%8,%9}, {%0,%1,%2,%3};" \
                 : "+f"((c)[0]), "+f"((c)[1]), "+f"((c)[2]), "+f"((c)[3]) \
                 : "r"(a0), "r"(a1), "r"(a2), "r"(a3), "r"(b0), "r"(b1))

// Shared tile geometry (both MMA kernels)
#define PITCH_B 272                  // bytes per 128-half row (17x16B: ldsm conflict-free)
#define T_BYTES (128 * PITCH_B)      // 34816 per tile
#define G_SMEM  (4 * T_BYTES + 512)  // 4 tiles + bias

// ---------------------------------------------------------------------------
// Split a float4 into hi/lo bf16x2 pairs (packed as uint2 for 8B smem stores)
// ---------------------------------------------------------------------------
__device__ __forceinline__ void split4(float4 v, uint2& hh, uint2& ll)
{
    __nv_bfloat162 pa = __floats2bfloat162_rn(v.x, v.y);
    __nv_bfloat162 pb = __floats2bfloat162_rn(v.z, v.w);
    __nv_bfloat162 la = __floats2bfloat162_rn(v.x - __low2float(pa),
                                              v.y - __high2float(pa));
    __nv_bfloat162 lb = __floats2bfloat162_rn(v.z - __low2float(pb),
                                              v.w - __high2float(pb));
    hh.x = *reinterpret_cast<unsigned*>(&pa);
    hh.y = *reinterpret_cast<unsigned*>(&pb);
    ll.x = *reinterpret_cast<unsigned*>(&la);
    ll.y = *reinterpret_cast<unsigned*>(&lb);
}

// ---------------------------------------------------------------------------
// Kernel 1: projection via split-bf16 HMMA.
//   out[r][d] = sum_k x[r][k] * W[d][k] + b[d]   (x: A operand, W: B operand)
// CTA tile M=128 rows x N=128 (all d), K=128. blockIdx<128 -> Q, else K.
// ---------------------------------------------------------------------------
#define SM_AH   0
#define SM_AL   (T_BYTES)
#define SM_BH   (2 * T_BYTES)
#define SM_BL   (3 * T_BYTES)
#define SM_BIAS (4 * T_BYTES)

__global__ void __launch_bounds__(256, 1)
proj_mma_kernel(const float* __restrict__ x_c,
                const float* __restrict__ x_n,
                const float* __restrict__ Wq,
                const float* __restrict__ bq,
                const float* __restrict__ Wk,
                const float* __restrict__ bk)
{
    extern __shared__ char smem[];
    const unsigned sb = smem_u32(smem);
    const int tid  = threadIdx.x;
    const int wid  = tid >> 5;
    const int lane = tid & 31;
    const int wm   = (wid & 3) * 32;
    const int wn   = (wid >> 2) * 64;

    const int which = (blockIdx.x >= 128);
    const int row0  = (blockIdx.x & 127) * 128;        // global row in [0,16384)
    const float* x    = which ? x_n : x_c;
    const float* W    = which ? Wk  : Wq;
    const float* bias = which ? bk  : bq;
    __nv_bfloat16* oh = which ? g_Kh : g_Qh;
    __nv_bfloat16* ol = which ? g_Kl : g_Ql;
    const float scale = which ? 1.0f : ENTMAX_SCALE;

    // Stage x tile (M rows) and W tile (N rows), splitting fp32 -> hi/lo bf16.
    {
        const float4* xs = (const float4*)(x + (long)row0 * DD);
        const float4* ws = (const float4*)W;
        #pragma unroll
        for (int i = 0; i < 16; i++) {
            int idx = i * 256 + tid;            // idx = row*32 + c4
            int r = idx >> 5, c4 = idx & 31;
            uint2 hh, ll;
            split4(xs[idx], hh, ll);
            *(uint2*)(smem + SM_AH + r * PITCH_B + c4 * 8) = hh;
            *(uint2*)(smem + SM_AL + r * PITCH_B + c4 * 8) = ll;
            split4(ws[idx], hh, ll);
            *(uint2*)(smem + SM_BH + r * PITCH_B + c4 * 8) = hh;
            *(uint2*)(smem + SM_BL + r * PITCH_B + c4 * 8) = ll;
        }
        if (tid < 128) ((float*)(smem + SM_BIAS))[tid] = bias[tid];
    }
    __syncthreads();

    float acc[2][8][4];
    #pragma unroll
    for (int mt = 0; mt < 2; mt++)
        #pragma unroll
        for (int nt = 0; nt < 8; nt++)
            #pragma unroll
            for (int j = 0; j < 4; j++) acc[mt][nt][j] = 0.f;

    const int lrow = lane & 15;
    const int lcol = (lane >> 4) * 8;

    #pragma unroll
    for (int pass = 0; pass < 3; pass++) {
        const int aoff = (pass == 2) ? SM_AL : SM_AH;
        const int boff = (pass == 1) ? SM_BL : SM_BH;

        unsigned a[2][8][4];
        #pragma unroll
        for (int mt = 0; mt < 2; mt++)
            #pragma unroll
            for (int kt = 0; kt < 8; kt++) {
                unsigned addr = sb + aoff + (wm + mt * 16 + lrow) * PITCH_B
                              + (kt * 16 + lcol) * 2;
                LDSM_X4(a[mt][kt][0], a[mt][kt][1], a[mt][kt][2], a[mt][kt][3], addr);
            }

        #pragma unroll
        for (int ntp = 0; ntp < 4; ntp++) {
            #pragma unroll
            for (int kt = 0; kt < 8; kt++) {
                unsigned b0, b1, b2, b3;
                unsigned addr = sb + boff + (wn + ntp * 16 + lrow) * PITCH_B
                              + (kt * 16 + lcol) * 2;
                LDSM_X4(b0, b1, b2, b3, addr);
                #pragma unroll
                for (int mt = 0; mt < 2; mt++) {
                    MMA_BF16(acc[mt][2 * ntp + 0], a[mt][kt][0], a[mt][kt][1],
                             a[mt][kt][2], a[mt][kt][3], b0, b2);
                    MMA_BF16(acc[mt][2 * ntp + 1], a[mt][kt][0], a[mt][kt][1],
                             a[mt][kt][2], a[mt][kt][3], b1, b3);
                }
            }
        }
    }

    // Epilogue: +bias, *scale, split to hi/lo bf16, store [row][d].
    const int crow = lane >> 2;
    const int ccol = (lane & 3) * 2;
    const float* bs = (const float*)(smem + SM_BIAS);
    #pragma unroll
    for (int mt = 0; mt < 2; mt++)
        #pragma unroll
        for (int nt = 0; nt < 8; nt++) {
            int col = wn + nt * 8 + ccol;
            float b0 = bs[col], b1 = bs[col + 1];
            #pragma unroll
            for (int half = 0; half < 2; half++) {
                long row = row0 + wm + mt * 16 + crow + half * 8;
                float v0 = (acc[mt][nt][2 * half + 0] + b0) * scale;
                float v1 = (acc[mt][nt][2 * half + 1] + b1) * scale;
                __nv_bfloat162 ph = __floats2bfloat162_rn(v0, v1);
                __nv_bfloat162 pl = __floats2bfloat162_rn(v0 - __low2float(ph),
                                                          v1 - __high2float(ph));
                *(__nv_bfloat162*)(oh + row * DD + col) = ph;
                *(__nv_bfloat162*)(ol + row * DD + col) = pl;
            }
        }
}

// ---------------------------------------------------------------------------
// Kernel 2: split-bf16 HMMA GEMM  g_A[b][m][n] = Qs[b,m] . K[b,n]
// CTA: 256 threads (8 warps, 4x2), tile M=128 x N=128, K=128 resident.
// Batch-sliced: bbase selects the 4-batch group (A-slab stays in L2).
// ---------------------------------------------------------------------------
#define SM_QH   0
#define SM_QL   (T_BYTES)
#define SM_KH   (2 * T_BYTES)
#define SM_KL   (3 * T_BYTES)

__device__ __forceinline__ void stage_tile_async(unsigned sdst,
                                                 const __nv_bfloat16* src, int tid)
{
    #pragma unroll
    for (int i = 0; i < 8; i++) {
        int idx = i * 256 + tid;                 // idx = row*16 + c8
        int row = idx >> 4, c8 = idx & 15;
        unsigned dst = sdst + row * PITCH_B + c8 * 16;
        asm volatile("cp.async.cg.shared.global [%0], [%1], 16;"
                     :: "r"(dst), "l"((const char*)src + (long)idx * 16) : "memory");
    }
}

__global__ void __launch_bounds__(256, 1)
qk_mma_kernel(int bbase)
{
    extern __shared__ char smem[];
    const unsigned sb = smem_u32(smem);
    const int tid  = threadIdx.x;
    const int wid  = tid >> 5;
    const int lane = tid & 31;
    const int wm   = (wid & 3) * 32;
    const int wn   = (wid >> 2) * 64;

    const int b   = bbase + (blockIdx.x >> 8);
    const int rem = blockIdx.x & 255;
    const int m0  = (rem >> 4) << 7;
    const int n0  = (rem & 15) << 7;

    const long qb = (long)(b * NN + m0) * DD;
    const long kb = (long)(b * NN + n0) * DD;
    stage_tile_async(sb + SM_QH, g_Qh + qb, tid);
    stage_tile_async(sb + SM_QL, g_Ql + qb, tid);
    stage_tile_async(sb + SM_KH, g_Kh + kb, tid);
    stage_tile_async(sb + SM_KL, g_Kl + kb, tid);
    asm volatile("cp.async.commit_group;" ::: "memory");
    asm volatile("cp.async.wait_group 0;" ::: "memory");
    __syncthreads();

    float acc[2][8][4];
    #pragma unroll
    for (int mt = 0; mt < 2; mt++)
        #pragma unroll
        for (int nt = 0; nt < 8; nt++)
            #pragma unroll
            for (int j = 0; j < 4; j++) acc[mt][nt][j] = 0.f;

    const int lrow = lane & 15;
    const int lcol = (lane >> 4) * 8;

    #pragma unroll
    for (int pass = 0; pass < 3; pass++) {
        const int qoff = (pass == 2) ? SM_QL : SM_QH;
        const int koff = (pass == 1) ? SM_KL : SM_KH;

        unsigned a[2][8][4];
        #pragma unroll
        for (int mt = 0; mt < 2; mt++)
            #pragma unroll
            for (int kt = 0; kt < 8; kt++) {
                unsigned addr = sb + qoff + (wm + mt * 16 + lrow) * PITCH_B
                              + (kt * 16 + lcol) * 2;
                LDSM_X4(a[mt][kt][0], a[mt][kt][1], a[mt][kt][2], a[mt][kt][3], addr);
            }

        #pragma unroll
        for (int ntp = 0; ntp < 4; ntp++) {
            #pragma unroll
            for (int kt = 0; kt < 8; kt++) {
                unsigned b0, b1, b2, b3;
                unsigned addr = sb + koff + (wn + ntp * 16 + lrow) * PITCH_B
                              + (kt * 16 + lcol) * 2;
                LDSM_X4(b0, b1, b2, b3, addr);
                #pragma unroll
                for (int mt = 0; mt < 2; mt++) {
                    MMA_BF16(acc[mt][2 * ntp + 0], a[mt][kt][0], a[mt][kt][1],
                             a[mt][kt][2], a[mt][kt][3], b0, b2);
                    MMA_BF16(acc[mt][2 * ntp + 1], a[mt][kt][0], a[mt][kt][1],
                             a[mt][kt][2], a[mt][kt][3], b1, b3);
                }
            }
        }
    }

    const int crow = lane >> 2;
    const int ccol = (lane & 3) * 2;
    float* base = g_A + (long)(b * NN + m0 + wm) * NN + n0 + wn;
    #pragma unroll
    for (int mt = 0; mt < 2; mt++)
        #pragma unroll
        for (int nt = 0; nt < 8; nt++) {
            float* p0 = base + (long)(mt * 16 + crow) * NN + nt * 8 + ccol;
            *(float2*)p0              = make_float2(acc[mt][nt][0], acc[mt][nt][1]);
            *(float2*)(p0 + 8LL * NN) = make_float2(acc[mt][nt][2], acc[mt][nt][3]);
        }
}

// ---------------------------------------------------------------------------
// Kernel 3: 1.5-entmax per row (sort-free monotone Newton), streaming g_A.
// Batch-sliced to read the A-slab while it is still L2-resident.
// ---------------------------------------------------------------------------
__global__ void __launch_bounds__(256)
entmax_kernel(float* __restrict__ out, int bbase)
{
    const int tid = threadIdx.x;
    const int tx  = tid & 31;
    const int wy  = tid >> 5;
    const long row = (long)(bbase + (blockIdx.x >> 8)) * NN
                   + (blockIdx.x & 255) * 8 + wy;

    const float4* src = (const float4*)(g_A + row * NN);
    float acc[64];
    float zmax = -1e30f;
    #pragma unroll
    for (int t = 0; t < 16; t++) {
        float4 v = src[t * 32 + tx];
        acc[t*4+0] = v.x; acc[t*4+1] = v.y; acc[t*4+2] = v.z; acc[t*4+3] = v.w;
        zmax = fmaxf(zmax, fmaxf(fmaxf(v.x, v.y), fmaxf(v.z, v.w)));
    }
    #pragma unroll
    for (int o = 16; o; o >>= 1)
        zmax = fmaxf(zmax, __shfl_xor_sync(0xffffffffu, zmax, o));
    #pragma unroll
    for (int i = 0; i < 64; i++) acc[i] -= zmax;

    // tau = root of f(tau) = sum((z-tau)_+^2) - 1 (convex, decreasing);
    // monotone Newton from tau=-1 never overshoots.
    float tau = -1.0f;
    for (int it = 0; it < 50; it++) {
        float s1 = 0.f, s2 = 0.f;
        #pragma unroll
        for (int i = 0; i < 64; i++) {
            float d = fmaxf(acc[i] - tau, 0.f);
            s1 += d;
            s2 = fmaf(d, d, s2);
        }
        #pragma unroll
        for (int o = 16; o; o >>= 1) {
            s1 += __shfl_xor_sync(0xffffffffu, s1, o);
            s2 += __shfl_xor_sync(0xffffffffu, s2, o);
        }
        float f = s2 - 1.0f;
        if (f < 1e-5f) break;
        tau += f / (2.0f * s1);
    }

    float4* dst = (float4*)(out + row * NN);
    #pragma unroll
    for (int t = 0; t < 16; t++) {
        float d0 = fmaxf(acc[t*4+0] - tau, 0.f);
        float d1 = fmaxf(acc[t*4+1] - tau, 0.f);
        float d2 = fmaxf(acc[t*4+2] - tau, 0.f);
        float d3 = fmaxf(acc[t*4+3] - tau, 0.f);
        dst[t * 32 + tx] = make_float4(d0*d0, d1*d1, d2*d2, d3*d3);
    }
}

// ---------------------------------------------------------------------------
extern "C" void kernel_launch(void* const* d_in, const int* in_sizes, int n_in,
                              void* d_out, int out_size)
{
    const float* x_c = (const float*)d_in[0];
    const float* x_n = (const float*)d_in[1];
    const float* Wq  = (const float*)d_in[2];
    const float* bq  = (const float*)d_in[3];
    const float* Wk  = (const float*)d_in[4];
    const float* bk  = (const float*)d_in[5];

    cudaFuncSetAttribute(proj_mma_kernel,
                         cudaFuncAttributeMaxDynamicSharedMemorySize, G_SMEM);
    cudaFuncSetAttribute(qk_mma_kernel,
                         cudaFuncAttributeMaxDynamicSharedMemorySize, G_SMEM);

    proj_mma_kernel<<<256, 256, G_SMEM>>>(x_c, x_n, Wq, bq, Wk, bk);

    // 2 slices of 4 batches: each slice's 67 MB logit slab fits in the
    // 126 MB L2, so the entmax read is served from L2, not DRAM.
    for (int s = 0; s < 2; s++) {
        qk_mma_kernel<<<4 * 256, 256, G_SMEM>>>(s * 4);
        entmax_kernel<<<4 * 256, 256>>>((float*)d_out, s * 4);
    }
}